// round 2
// baseline (speedup 1.0000x reference)
#include <cuda_runtime.h>
#include <math.h>

#define BSZ   16
#define SEQ   1024
#define DIM   512
#define NH    8
#define HD    64
#define MTOT  (BSZ*SEQ)
#define NEGV  (-4294967295.0f)

__device__ float g_buf[8u * MTOT * DIM];

// ---------------------------------------------------------------------------
// GEMM: C[M,512] = A[M,512] @ B  (TRANSB -> C = A @ B^T)
// Tiles 128x128x16, 256 threads, 8x8 micro-tile.
// ---------------------------------------------------------------------------
template<bool TRANSB, bool BIAS, bool RELU>
__global__ void __launch_bounds__(256) gemm512(const float* __restrict__ A,
                                               const float* __restrict__ B,
                                               const float* __restrict__ bias,
                                               float* __restrict__ C) {
    __shared__ float Ast[16][132];   // A transposed: Ast[k][m]
    __shared__ float Bs[16][132];    // Bs[k][n]
    const int tid = threadIdx.x;
    const int tx = tid & 15, ty = tid >> 4;
    const int m0 = blockIdx.y * 128, n0 = blockIdx.x * 128;

    float acc[8][8];
#pragma unroll
    for (int i = 0; i < 8; i++)
#pragma unroll
        for (int j = 0; j < 8; j++) acc[i][j] = 0.f;

    for (int k0 = 0; k0 < 512; k0 += 16) {
        __syncthreads();
        // A tile 128x16 -> transposed (512 float4)
#pragma unroll
        for (int r = 0; r < 2; r++) {
            int f = tid + r * 256;
            int row = f >> 2, k4 = f & 3;
            float4 v = *(const float4*)(A + (size_t)(m0 + row) * 512 + k0 + k4 * 4);
            Ast[k4 * 4 + 0][row] = v.x;
            Ast[k4 * 4 + 1][row] = v.y;
            Ast[k4 * 4 + 2][row] = v.z;
            Ast[k4 * 4 + 3][row] = v.w;
        }
        // B tile (16x128 or 128x16-transposed), 512 float4
        if (!TRANSB) {
#pragma unroll
            for (int r = 0; r < 2; r++) {
                int f = tid + r * 256;
                int kk = f >> 5, n4 = f & 31;
                float4 v = *(const float4*)(B + (size_t)(k0 + kk) * 512 + n0 + n4 * 4);
                *(float4*)&Bs[kk][n4 * 4] = v;
            }
        } else {
#pragma unroll
            for (int r = 0; r < 2; r++) {
                int f = tid + r * 256;
                int n = f >> 2, k4 = f & 3;
                float4 v = *(const float4*)(B + (size_t)(n0 + n) * 512 + k0 + k4 * 4);
                Bs[k4 * 4 + 0][n] = v.x;
                Bs[k4 * 4 + 1][n] = v.y;
                Bs[k4 * 4 + 2][n] = v.z;
                Bs[k4 * 4 + 3][n] = v.w;
            }
        }
        __syncthreads();
#pragma unroll
        for (int kk = 0; kk < 16; kk++) {
            float4 a0 = *(float4*)&Ast[kk][ty * 8];
            float4 a1 = *(float4*)&Ast[kk][ty * 8 + 4];
            float4 b0 = *(float4*)&Bs[kk][tx * 8];
            float4 b1 = *(float4*)&Bs[kk][tx * 8 + 4];
            float a[8] = {a0.x, a0.y, a0.z, a0.w, a1.x, a1.y, a1.z, a1.w};
            float b[8] = {b0.x, b0.y, b0.z, b0.w, b1.x, b1.y, b1.z, b1.w};
#pragma unroll
            for (int i = 0; i < 8; i++)
#pragma unroll
                for (int j = 0; j < 8; j++) acc[i][j] += a[i] * b[j];
        }
    }
    // Epilogue
    float bv0[8];
    if (BIAS) {
#pragma unroll
        for (int j = 0; j < 8; j++) bv0[j] = bias[n0 + tx * 8 + j];
    }
#pragma unroll
    for (int i = 0; i < 8; i++) {
        int row = m0 + ty * 8 + i;
        int col = n0 + tx * 8;
        float v[8];
#pragma unroll
        for (int j = 0; j < 8; j++) {
            v[j] = acc[i][j];
            if (BIAS) v[j] += bv0[j];
            if (RELU) v[j] = fmaxf(v[j], 0.f);
        }
        *(float4*)(C + (size_t)row * 512 + col)     = make_float4(v[0], v[1], v[2], v[3]);
        *(float4*)(C + (size_t)row * 512 + col + 4) = make_float4(v[4], v[5], v[6], v[7]);
    }
}

// ---------------------------------------------------------------------------
// Flash attention: one block = 128 query rows of one (b,h).
// 256 threads, 4q x 8k micro-tile (same map reused for 4q x 8d in PV).
// Q and K stored transposed in smem so all operand loads are float4.
// ---------------------------------------------------------------------------
__global__ void __launch_bounds__(256) attn_kernel(const float* __restrict__ Q,
                                                   const float* __restrict__ K,
                                                   const float* __restrict__ V,
                                                   const unsigned char* __restrict__ mask,
                                                   float* __restrict__ O) {
    extern __shared__ float sm[];
    float* Qt = sm;                       // Qt[kk][q]  64 x 132
    float* Kt = sm + 64 * 132;            // Kt[kk][c]  64 x 68
    float* Vs = Kt + 64 * 68;             // Vs[c][d]   64 x 68
    float* Ps = Vs + 64 * 68;             // Ps[q][c]  128 x 68

    const int tid = threadIdx.x;
    const int txk = tid & 7;              // key/d group (8 wide)
    const int tyq = tid >> 3;             // query group (0..31, 4 rows each)
    const int q0 = blockIdx.x * 128;
    const int h  = blockIdx.y;
    const int b  = blockIdx.z;
    const float inv_temp = 1.0f / (8.0f + 1e-6f);

    // Load Q tile 128x64, transposed (2048 float4)
#pragma unroll
    for (int r = 0; r < 8; r++) {
        int f = tid + r * 256;
        int row = f >> 4, k4 = f & 15;
        float4 v = *(const float4*)(Q + ((size_t)b * SEQ + q0 + row) * DIM + h * HD + k4 * 4);
        Qt[(k4 * 4 + 0) * 132 + row] = v.x;
        Qt[(k4 * 4 + 1) * 132 + row] = v.y;
        Qt[(k4 * 4 + 2) * 132 + row] = v.z;
        Qt[(k4 * 4 + 3) * 132 + row] = v.w;
    }

    float m[4], l[4], o[4][8];
#pragma unroll
    for (int i = 0; i < 4; i++) {
        m[i] = -INFINITY; l[i] = 0.f;
#pragma unroll
        for (int j = 0; j < 8; j++) o[i][j] = 0.f;
    }

    for (int kb = 0; kb < SEQ; kb += 64) {
        __syncthreads();   // protect Kt/Vs (and Ps from previous PV)
        // K transposed + V tiles: 64x64 each (1024 float4 each)
#pragma unroll
        for (int r = 0; r < 4; r++) {
            int f = tid + r * 256;
            int row = f >> 4, k4 = f & 15;
            size_t goff = ((size_t)b * SEQ + kb + row) * DIM + h * HD + k4 * 4;
            float4 kv = *(const float4*)(K + goff);
            Kt[(k4 * 4 + 0) * 68 + row] = kv.x;
            Kt[(k4 * 4 + 1) * 68 + row] = kv.y;
            Kt[(k4 * 4 + 2) * 68 + row] = kv.z;
            Kt[(k4 * 4 + 3) * 68 + row] = kv.w;
            float4 vv = *(const float4*)(V + goff);
            *(float4*)&Vs[row * 68 + k4 * 4] = vv;
        }
        __syncthreads();

        // S = Q K^T  (4q x 8k per thread)
        float s[4][8];
#pragma unroll
        for (int i = 0; i < 4; i++)
#pragma unroll
            for (int j = 0; j < 8; j++) s[i][j] = 0.f;
#pragma unroll 8
        for (int kk = 0; kk < 64; kk++) {
            float4 av = *(float4*)&Qt[kk * 132 + tyq * 4];
            float4 b0 = *(float4*)&Kt[kk * 68 + txk * 8];
            float4 b1 = *(float4*)&Kt[kk * 68 + txk * 8 + 4];
            float a[4] = {av.x, av.y, av.z, av.w};
            float bb[8] = {b0.x, b0.y, b0.z, b0.w, b1.x, b1.y, b1.z, b1.w};
#pragma unroll
            for (int i = 0; i < 4; i++)
#pragma unroll
                for (int j = 0; j < 8; j++) s[i][j] += a[i] * bb[j];
        }

        // scale + mask (8 key columns at kb + txk*8)
        unsigned long long mk8 = *(const unsigned long long*)(mask + (size_t)b * SEQ + kb + txk * 8);
#pragma unroll
        for (int j = 0; j < 8; j++) {
            bool masked = ((mk8 >> (8 * j)) & 0xffu) != 0;
#pragma unroll
            for (int i = 0; i < 4; i++) {
                float sv = s[i][j] * inv_temp;
                s[i][j] = masked ? NEGV : sv;
            }
        }

        // Online softmax (row spread over 8 lanes: txk)
#pragma unroll
        for (int i = 0; i < 4; i++) {
            float tm = s[i][0];
#pragma unroll
            for (int j = 1; j < 8; j++) tm = fmaxf(tm, s[i][j]);
            tm = fmaxf(tm, __shfl_xor_sync(0xffffffffu, tm, 4));
            tm = fmaxf(tm, __shfl_xor_sync(0xffffffffu, tm, 2));
            tm = fmaxf(tm, __shfl_xor_sync(0xffffffffu, tm, 1));
            float mn = fmaxf(m[i], tm);
            float alpha = __expf(m[i] - mn);
            m[i] = mn;
            float rs = 0.f;
#pragma unroll
            for (int j = 0; j < 8; j++) {
                float p = __expf(s[i][j] - mn);
                s[i][j] = p;
                rs += p;
            }
            rs += __shfl_xor_sync(0xffffffffu, rs, 4);
            rs += __shfl_xor_sync(0xffffffffu, rs, 2);
            rs += __shfl_xor_sync(0xffffffffu, rs, 1);
            l[i] = l[i] * alpha + rs;
#pragma unroll
            for (int j = 0; j < 8; j++) o[i][j] *= alpha;
            // store P fragment (2 float4 per row)
            *(float4*)&Ps[(tyq * 4 + i) * 68 + txk * 8]     = make_float4(s[i][0], s[i][1], s[i][2], s[i][3]);
            *(float4*)&Ps[(tyq * 4 + i) * 68 + txk * 8 + 4] = make_float4(s[i][4], s[i][5], s[i][6], s[i][7]);
        }
        __syncthreads();

        // O += P V  (4q x 8d per thread)
#pragma unroll 8
        for (int cc = 0; cc < 64; cc++) {
            float4 b0 = *(float4*)&Vs[cc * 68 + txk * 8];
            float4 b1 = *(float4*)&Vs[cc * 68 + txk * 8 + 4];
            float bb[8] = {b0.x, b0.y, b0.z, b0.w, b1.x, b1.y, b1.z, b1.w};
            float a0 = Ps[(tyq * 4 + 0) * 68 + cc];
            float a1 = Ps[(tyq * 4 + 1) * 68 + cc];
            float a2 = Ps[(tyq * 4 + 2) * 68 + cc];
            float a3 = Ps[(tyq * 4 + 3) * 68 + cc];
            float a[4] = {a0, a1, a2, a3};
#pragma unroll
            for (int i = 0; i < 4; i++)
#pragma unroll
                for (int j = 0; j < 8; j++) o[i][j] += a[i] * bb[j];
        }
    }

    // Write V_att[b][q][h*64 + d]
#pragma unroll
    for (int i = 0; i < 4; i++) {
        float inv_l = 1.0f / l[i];
        float* dst = O + ((size_t)b * SEQ + q0 + tyq * 4 + i) * DIM + h * HD + txk * 8;
        *(float4*)dst       = make_float4(o[i][0] * inv_l, o[i][1] * inv_l, o[i][2] * inv_l, o[i][3] * inv_l);
        *(float4*)(dst + 4) = make_float4(o[i][4] * inv_l, o[i][5] * inv_l, o[i][6] * inv_l, o[i][7] * inv_l);
    }
}

// ---------------------------------------------------------------------------
// Fused residual add + LayerNorm over rows of 512.
// ---------------------------------------------------------------------------
__global__ void __launch_bounds__(256) ln_residual(const float* __restrict__ A,
                                                   const float* __restrict__ Bm,
                                                   const float* __restrict__ g,
                                                   const float* __restrict__ beta,
                                                   float* __restrict__ out) {
    const int row = blockIdx.x;
    const int tid = threadIdx.x;
    const size_t base = (size_t)row * 512;
    float e0 = A[base + tid]       + Bm[base + tid];
    float e1 = A[base + tid + 256] + Bm[base + tid + 256];
    float s  = e0 + e1;
    float s2 = e0 * e0 + e1 * e1;
#pragma unroll
    for (int off = 16; off; off >>= 1) {
        s  += __shfl_xor_sync(0xffffffffu, s, off);
        s2 += __shfl_xor_sync(0xffffffffu, s2, off);
    }
    __shared__ float ws[8], ws2[8];
    const int wid = tid >> 5, lane = tid & 31;
    if (lane == 0) { ws[wid] = s; ws2[wid] = s2; }
    __syncthreads();
    float ts = 0.f, ts2 = 0.f;
#pragma unroll
    for (int w = 0; w < 8; w++) { ts += ws[w]; ts2 += ws2[w]; }
    float mu  = ts * (1.0f / 512.0f);
    float var = ts2 * (1.0f / 512.0f) - mu * mu;
    float rsd = rsqrtf(var + 1e-5f);
    out[base + tid]       = (e0 - mu) * rsd * g[tid]       + beta[tid];
    out[base + tid + 256] = (e1 - mu) * rsd * g[tid + 256] + beta[tid + 256];
}

// ---------------------------------------------------------------------------
extern "C" void kernel_launch(void* const* d_in, const int* in_sizes, int n_in,
                              void* d_out, int out_size) {
    const float* query = (const float*)d_in[0];
    const float* key   = (const float*)d_in[1];
    const float* value = (const float*)d_in[2];
    const unsigned char* mask = (const unsigned char*)d_in[3];
    const float* Wq = (const float*)d_in[4];
    const float* Wk = (const float*)d_in[5];
    const float* Wv = (const float*)d_in[6];
    const float* Wo = (const float*)d_in[7];
    const float* w1 = (const float*)d_in[8];
    const float* b1 = (const float*)d_in[9];
    const float* w2 = (const float*)d_in[10];
    const float* b2 = (const float*)d_in[11];
    const float* w3 = (const float*)d_in[12];
    const float* b3 = (const float*)d_in[13];
    const float* lng = (const float*)d_in[14];
    const float* lnb = (const float*)d_in[15];
    float* out = (float*)d_out;

    float* base = nullptr;
    cudaGetSymbolAddress((void**)&base, g_buf);
    const size_t N = (size_t)MTOT * DIM;
    float* Qb = base;
    float* Kb = base + 1 * N;
    float* Vb = base + 2 * N;
    float* Va = base + 3 * N;
    float* T0 = base + 4 * N;
    float* X1 = base + 5 * N;
    float* H1 = base + 6 * N;
    float* X2 = base + 7 * N;

    dim3 gg(4, 128), gb(256);

    // QKV projections
    gemm512<false, false, false><<<gg, gb>>>(query, Wq, nullptr, Qb);
    gemm512<false, false, false><<<gg, gb>>>(key,   Wk, nullptr, Kb);
    gemm512<false, false, false><<<gg, gb>>>(value, Wv, nullptr, Vb);

    // Fused attention: 128-query tiles
    const int attn_smem = (64 * 132 + 64 * 68 + 64 * 68 + 128 * 68) * (int)sizeof(float);
    cudaFuncSetAttribute(attn_kernel, cudaFuncAttributeMaxDynamicSharedMemorySize, attn_smem);
    attn_kernel<<<dim3(SEQ / 128, NH, BSZ), 256, attn_smem>>>(Qb, Kb, Vb, mask, Va);

    // Output projection + residual LN
    gemm512<false, false, false><<<gg, gb>>>(Va, Wo, nullptr, T0);
    ln_residual<<<MTOT, 256>>>(query, T0, lng, lnb, X1);

    // FFN
    gemm512<true, true, true ><<<gg, gb>>>(X1, w1, b1, H1);
    gemm512<true, true, false><<<gg, gb>>>(H1, w2, b2, T0);
    ln_residual<<<MTOT, 256>>>(T0, X1, lng, lnb, X2);

    // Final projection
    gemm512<true, true, false><<<gg, gb>>>(X2, w3, b3, out);
}

// round 4
// speedup vs baseline: 1.0088x; 1.0088x over previous
#include <cuda_runtime.h>
#include <cuda_bf16.h>
#include <math.h>
#include <stdint.h>

#define BSZ   16
#define SEQ   1024
#define DIM   512
#define NH    8
#define HD    64
#define MTOT  (BSZ*SEQ)
#define NEGV  (-4294967295.0f)

__device__ float g_buf[8u * MTOT * DIM];                 // activations scratch
__device__ __nv_bfloat16 g_wbuf[7u * 2u * 512u * 512u];  // weights bf16 hi/lo, [N,K]

// ---------------------------------------------------------------------------
// helpers
// ---------------------------------------------------------------------------
__device__ __forceinline__ uint32_t smem_u32(const void* p) {
    uint32_t a;
    asm("{ .reg .u64 t; cvta.to.shared.u64 t, %1; cvt.u32.u64 %0, t; }" : "=r"(a) : "l"(p));
    return a;
}

__device__ __forceinline__ void ldsm_x4(uint32_t& r0, uint32_t& r1, uint32_t& r2, uint32_t& r3, uint32_t a) {
    asm volatile("ldmatrix.sync.aligned.m8n8.x4.shared.b16 {%0,%1,%2,%3}, [%4];"
                 : "=r"(r0), "=r"(r1), "=r"(r2), "=r"(r3) : "r"(a));
}
__device__ __forceinline__ void ldsm_x2(uint32_t& r0, uint32_t& r1, uint32_t a) {
    asm volatile("ldmatrix.sync.aligned.m8n8.x2.shared.b16 {%0,%1}, [%2];"
                 : "=r"(r0), "=r"(r1) : "r"(a));
}
__device__ __forceinline__ void mma_bf16(float* d, const uint32_t* a, const uint32_t* b) {
    asm volatile("mma.sync.aligned.m16n8k16.row.col.f32.bf16.bf16.f32 "
                 "{%0,%1,%2,%3}, {%4,%5,%6,%7}, {%8,%9}, {%0,%1,%2,%3};"
                 : "+f"(d[0]), "+f"(d[1]), "+f"(d[2]), "+f"(d[3])
                 : "r"(a[0]), "r"(a[1]), "r"(a[2]), "r"(a[3]), "r"(b[0]), "r"(b[1]));
}
#define CP_ASYNC16(s, g) \
    asm volatile("cp.async.cg.shared.global [%0], [%1], 16;" :: "r"(s), "l"(g) : "memory")
#define CP_COMMIT()  asm volatile("cp.async.commit_group;" ::: "memory")
#define CP_WAIT0()   asm volatile("cp.async.wait_group 0;" ::: "memory")

__device__ __forceinline__ void split1(float x, unsigned short& h, unsigned short& l) {
    __nv_bfloat16 hb = __float2bfloat16(x);
    float r = x - __bfloat162float(hb);
    __nv_bfloat16 lb = __float2bfloat16(r);
    h = __bfloat16_as_ushort(hb);
    l = __bfloat16_as_ushort(lb);
}

// ---------------------------------------------------------------------------
// Weight conversion: bf16 hi/lo in [N,K] K-major
// ---------------------------------------------------------------------------
__global__ void __launch_bounds__(256) convw_nt(const float* __restrict__ in,
                                                __nv_bfloat16* __restrict__ hi,
                                                __nv_bfloat16* __restrict__ lo) {
    int i = blockIdx.x * 256 + threadIdx.x;
    float4 v = ((const float4*)in)[i];
    unsigned short h[4], l[4];
    split1(v.x, h[0], l[0]); split1(v.y, h[1], l[1]);
    split1(v.z, h[2], l[2]); split1(v.w, h[3], l[3]);
    uint2 hp = make_uint2((uint32_t)h[0] | ((uint32_t)h[1] << 16),
                          (uint32_t)h[2] | ((uint32_t)h[3] << 16));
    uint2 lp = make_uint2((uint32_t)l[0] | ((uint32_t)l[1] << 16),
                          (uint32_t)l[2] | ((uint32_t)l[3] << 16));
    *(uint2*)(hi + (size_t)i * 4) = hp;
    *(uint2*)(lo + (size_t)i * 4) = lp;
}

__global__ void __launch_bounds__(256) convw_t(const float* __restrict__ in,
                                               __nv_bfloat16* __restrict__ hi,
                                               __nv_bfloat16* __restrict__ lo) {
    __shared__ float t[32][33];
    const int bx = blockIdx.x * 32;   // k block
    const int by = blockIdx.y * 32;   // n block
    const int tx = threadIdx.x & 31, tr = threadIdx.x >> 5;
#pragma unroll
    for (int i = 0; i < 4; i++) {
        int r = tr + i * 8;
        t[r][tx] = in[(size_t)(bx + r) * 512 + by + tx];
    }
    __syncthreads();
#pragma unroll
    for (int i = 0; i < 4; i++) {
        int r = tr + i * 8;
        float x = t[tx][r];
        unsigned short h, l;
        split1(x, h, l);
        size_t o = (size_t)(by + r) * 512 + bx + tx;
        hi[o] = __ushort_as_bfloat16(h);
        lo[o] = __ushort_as_bfloat16(l);
    }
}

// ---------------------------------------------------------------------------
// HMMA GEMM: C[M,512] = A[M,512] fp32 @ B[N,K]^T (bf16 hi/lo, 3-term split)
// CTA 128x128, 8 warps (2m x 4n), warp tile 64x32, K chunks of 32, dbl-buffer.
// smem rows padded to 40 halves (80 B) -> conflict-free ldmatrix.
// ---------------------------------------------------------------------------
#define RS      80          // row stride bytes
#define OFF_AH  0
#define OFF_AL  10240
#define OFF_BH  20480
#define OFF_BL  30720
#define STG     40960       // stage bytes
#define GM_SMEM (2 * STG)

template<bool BIAS, bool RELU>
__global__ void __launch_bounds__(256) gemm_mma(const float* __restrict__ A,
                                                const __nv_bfloat16* __restrict__ Bh,
                                                const __nv_bfloat16* __restrict__ Bl,
                                                const float* __restrict__ bias,
                                                float* __restrict__ C) {
    extern __shared__ __align__(128) char smem[];
    const uint32_t sb = smem_u32(smem);
    const int tid = threadIdx.x;
    const int lane = tid & 31, wid = tid >> 5;
    const int wm = wid >> 2, wn = wid & 3;       // 2 x 4 warps
    const int m0 = blockIdx.y * 128, n0 = blockIdx.x * 128;

    float acc[4][4][4];
#pragma unroll
    for (int i = 0; i < 4; i++)
#pragma unroll
        for (int j = 0; j < 4; j++)
#pragma unroll
            for (int v = 0; v < 4; v++) acc[i][j][v] = 0.f;

    const int arow = tid >> 3, ac4 = tid & 7;    // A ld map (per f = tid + i*256)
    float4 va[4];

    // ---- helpers as lambdas
    auto loadA = [&](int c) {
#pragma unroll
        for (int i = 0; i < 4; i++) {
            int row = (tid + i * 256) >> 3;
            int c4  = (tid + i * 256) & 7;
            va[i] = *(const float4*)(A + (size_t)(m0 + row) * 512 + c * 32 + c4 * 4);
        }
    };
    auto storeA = [&](int p) {
#pragma unroll
        for (int i = 0; i < 4; i++) {
            int row = (tid + i * 256) >> 3;
            int c4  = (tid + i * 256) & 7;
            unsigned short h[4], l[4];
            split1(va[i].x, h[0], l[0]); split1(va[i].y, h[1], l[1]);
            split1(va[i].z, h[2], l[2]); split1(va[i].w, h[3], l[3]);
            uint2 hp = make_uint2((uint32_t)h[0] | ((uint32_t)h[1] << 16),
                                  (uint32_t)h[2] | ((uint32_t)h[3] << 16));
            uint2 lp = make_uint2((uint32_t)l[0] | ((uint32_t)l[1] << 16),
                                  (uint32_t)l[2] | ((uint32_t)l[3] << 16));
            uint32_t off = (uint32_t)(row * RS + c4 * 8);
            *(uint2*)(smem + p * STG + OFF_AH + off) = hp;
            *(uint2*)(smem + p * STG + OFF_AL + off) = lp;
        }
    };
    auto issueB = [&](int c, int p) {
#pragma unroll
        for (int i = 0; i < 4; i++) {
            int f = tid + i * 256;               // 0..1023
            int mat = f >> 9, g = f & 511;
            int row = g >> 2, q = g & 3;
            const __nv_bfloat16* src = (mat ? Bl : Bh) + (size_t)(n0 + row) * 512 + c * 32 + q * 8;
            uint32_t dst = sb + p * STG + (mat ? OFF_BL : OFF_BH) + row * RS + q * 16;
            CP_ASYNC16(dst, src);
        }
        CP_COMMIT();
    };

    // ---- prologue: chunk 0
    loadA(0);
    issueB(0, 0);
    storeA(0);
    CP_WAIT0();
    __syncthreads();

    for (int c = 0; c < 16; c++) {
        const int p = c & 1;
        if (c < 15) { loadA(c + 1); issueB(c + 1, p ^ 1); }

        const uint32_t stg = sb + p * STG;
#pragma unroll
        for (int kk = 0; kk < 2; kk++) {
            // B fragments: 4 n-tiles x (hi,lo)
            uint32_t bh[4][2], bl[4][2];
#pragma unroll
            for (int nt = 0; nt < 4; nt++) {
                uint32_t boff = (uint32_t)((wn * 32 + nt * 8 + (lane & 7)) * RS +
                                           (kk * 16 + ((lane >> 3) & 1) * 8) * 2);
                ldsm_x2(bh[nt][0], bh[nt][1], stg + OFF_BH + boff);
                ldsm_x2(bl[nt][0], bl[nt][1], stg + OFF_BL + boff);
            }
#pragma unroll
            for (int mt = 0; mt < 4; mt++) {
                uint32_t aoff = (uint32_t)((wm * 64 + mt * 16 + (lane & 15)) * RS +
                                           (kk * 16 + ((lane >> 4) & 1) * 8) * 2);
                uint32_t ah[4], al[4];
                ldsm_x4(ah[0], ah[1], ah[2], ah[3], stg + OFF_AH + aoff);
                ldsm_x4(al[0], al[1], al[2], al[3], stg + OFF_AL + aoff);
#pragma unroll
                for (int nt = 0; nt < 4; nt++) {
                    mma_bf16(acc[mt][nt], ah, bh[nt]);
                    mma_bf16(acc[mt][nt], ah, bl[nt]);
                    mma_bf16(acc[mt][nt], al, bh[nt]);
                }
            }
        }

        if (c < 15) {
            storeA(p ^ 1);
            CP_WAIT0();
            __syncthreads();
        }
    }

    // ---- epilogue
#pragma unroll
    for (int mt = 0; mt < 4; mt++) {
#pragma unroll
        for (int nt = 0; nt < 4; nt++) {
            int r0 = m0 + wm * 64 + mt * 16 + (lane >> 2);
            int cc = n0 + wn * 32 + nt * 8 + 2 * (lane & 3);
            float d0 = acc[mt][nt][0], d1 = acc[mt][nt][1];
            float d2 = acc[mt][nt][2], d3 = acc[mt][nt][3];
            if (BIAS) {
                float b0 = bias[cc], b1 = bias[cc + 1];
                d0 += b0; d1 += b1; d2 += b0; d3 += b1;
            }
            if (RELU) {
                d0 = fmaxf(d0, 0.f); d1 = fmaxf(d1, 0.f);
                d2 = fmaxf(d2, 0.f); d3 = fmaxf(d3, 0.f);
            }
            *(float2*)(C + (size_t)r0 * 512 + cc)       = make_float2(d0, d1);
            *(float2*)(C + (size_t)(r0 + 8) * 512 + cc) = make_float2(d2, d3);
        }
    }
}

// ---------------------------------------------------------------------------
// Flash attention (R1 version): 64q tile, 4x4 micro-tile.
// ---------------------------------------------------------------------------
__global__ void __launch_bounds__(256) attn_kernel(const float* __restrict__ Q,
                                                   const float* __restrict__ K,
                                                   const float* __restrict__ V,
                                                   const unsigned char* __restrict__ mask,
                                                   float* __restrict__ O) {
    extern __shared__ float sm[];
    float* Qs = sm;
    float* Kt = sm + 64 * 68;
    float* Vs = sm + 2 * 64 * 68;
    float* Ps = sm + 3 * 64 * 68;

    const int tid = threadIdx.x;
    const int tx = tid & 15, ty = tid >> 4;
    const int q0 = blockIdx.x * 64;
    const int h  = blockIdx.y;
    const int b  = blockIdx.z;
    const float inv_temp = 1.0f / (8.0f + 1e-6f);

#pragma unroll
    for (int r = 0; r < 4; r++) {
        int f = tid + r * 256;
        int row = f >> 4, k4 = f & 15;
        float4 v = *(const float4*)(Q + ((size_t)b * SEQ + q0 + row) * DIM + h * HD + k4 * 4);
        *(float4*)&Qs[row * 68 + k4 * 4] = v;
    }

    float m[4], l[4], o[4][4];
#pragma unroll
    for (int i = 0; i < 4; i++) {
        m[i] = -INFINITY; l[i] = 0.f;
#pragma unroll
        for (int j = 0; j < 4; j++) o[i][j] = 0.f;
    }

    for (int kb = 0; kb < SEQ; kb += 64) {
        __syncthreads();
#pragma unroll
        for (int r = 0; r < 4; r++) {
            int f = tid + r * 256;
            int row = f >> 4, k4 = f & 15;
            size_t goff = ((size_t)b * SEQ + kb + row) * DIM + h * HD + k4 * 4;
            float4 kv = *(const float4*)(K + goff);
            Kt[(k4 * 4 + 0) * 68 + row] = kv.x;
            Kt[(k4 * 4 + 1) * 68 + row] = kv.y;
            Kt[(k4 * 4 + 2) * 68 + row] = kv.z;
            Kt[(k4 * 4 + 3) * 68 + row] = kv.w;
            float4 vv = *(const float4*)(V + goff);
            *(float4*)&Vs[row * 68 + k4 * 4] = vv;
        }
        __syncthreads();

        float s[4][4];
#pragma unroll
        for (int i = 0; i < 4; i++)
#pragma unroll
            for (int j = 0; j < 4; j++) s[i][j] = 0.f;
#pragma unroll
        for (int kk = 0; kk < 64; kk++) {
            float4 bv = *(float4*)&Kt[kk * 68 + tx * 4];
            float bb[4] = {bv.x, bv.y, bv.z, bv.w};
#pragma unroll
            for (int i = 0; i < 4; i++) {
                float a = Qs[(ty * 4 + i) * 68 + kk];
#pragma unroll
                for (int j = 0; j < 4; j++) s[i][j] += a * bb[j];
            }
        }
        uchar4 mk = *(const uchar4*)(mask + (size_t)b * SEQ + kb + tx * 4);
        unsigned char mkb[4] = {mk.x, mk.y, mk.z, mk.w};
#pragma unroll
        for (int i = 0; i < 4; i++)
#pragma unroll
            for (int j = 0; j < 4; j++) {
                float sv = s[i][j] * inv_temp;
                s[i][j] = mkb[j] ? NEGV : sv;
            }

#pragma unroll
        for (int i = 0; i < 4; i++) {
            float tm = fmaxf(fmaxf(s[i][0], s[i][1]), fmaxf(s[i][2], s[i][3]));
#pragma unroll
            for (int off = 8; off; off >>= 1)
                tm = fmaxf(tm, __shfl_xor_sync(0xffffffffu, tm, off));
            float mn = fmaxf(m[i], tm);
            float alpha = __expf(m[i] - mn);
            m[i] = mn;
            float rs = 0.f;
#pragma unroll
            for (int j = 0; j < 4; j++) {
                float p = __expf(s[i][j] - mn);
                s[i][j] = p;
                rs += p;
            }
#pragma unroll
            for (int off = 8; off; off >>= 1)
                rs += __shfl_xor_sync(0xffffffffu, rs, off);
            l[i] = l[i] * alpha + rs;
#pragma unroll
            for (int j = 0; j < 4; j++) o[i][j] *= alpha;
            float4 pv;
            pv.x = s[i][0]; pv.y = s[i][1]; pv.z = s[i][2]; pv.w = s[i][3];
            *(float4*)&Ps[(ty * 4 + i) * 68 + tx * 4] = pv;
        }
        __syncthreads();

#pragma unroll
        for (int cc = 0; cc < 64; cc++) {
            float4 bv = *(float4*)&Vs[cc * 68 + tx * 4];
            float bb[4] = {bv.x, bv.y, bv.z, bv.w};
#pragma unroll
            for (int i = 0; i < 4; i++) {
                float a = Ps[(ty * 4 + i) * 68 + cc];
#pragma unroll
                for (int j = 0; j < 4; j++) o[i][j] += a * bb[j];
            }
        }
    }

#pragma unroll
    for (int i = 0; i < 4; i++) {
        float inv_l = 1.0f / l[i];
        float4 v;
        v.x = o[i][0] * inv_l; v.y = o[i][1] * inv_l;
        v.z = o[i][2] * inv_l; v.w = o[i][3] * inv_l;
        *(float4*)(O + ((size_t)b * SEQ + q0 + ty * 4 + i) * DIM + h * HD + tx * 4) = v;
    }
}

// ---------------------------------------------------------------------------
// Fused residual add + LayerNorm over rows of 512.
// ---------------------------------------------------------------------------
__global__ void __launch_bounds__(256) ln_residual(const float* __restrict__ A,
                                                   const float* __restrict__ Bm,
                                                   const float* __restrict__ g,
                                                   const float* __restrict__ beta,
                                                   float* __restrict__ out) {
    const int row = blockIdx.x;
    const int tid = threadIdx.x;
    const size_t base = (size_t)row * 512;
    float e0 = A[base + tid]       + Bm[base + tid];
    float e1 = A[base + tid + 256] + Bm[base + tid + 256];
    float s  = e0 + e1;
    float s2 = e0 * e0 + e1 * e1;
#pragma unroll
    for (int off = 16; off; off >>= 1) {
        s  += __shfl_xor_sync(0xffffffffu, s, off);
        s2 += __shfl_xor_sync(0xffffffffu, s2, off);
    }
    __shared__ float ws[8], ws2[8];
    const int wid = tid >> 5, lane = tid & 31;
    if (lane == 0) { ws[wid] = s; ws2[wid] = s2; }
    __syncthreads();
    float ts = 0.f, ts2 = 0.f;
#pragma unroll
    for (int w = 0; w < 8; w++) { ts += ws[w]; ts2 += ws2[w]; }
    float mu  = ts * (1.0f / 512.0f);
    float var = ts2 * (1.0f / 512.0f) - mu * mu;
    float rsd = rsqrtf(var + 1e-5f);
    out[base + tid]       = (e0 - mu) * rsd * g[tid]       + beta[tid];
    out[base + tid + 256] = (e1 - mu) * rsd * g[tid + 256] + beta[tid + 256];
}

// ---------------------------------------------------------------------------
extern "C" void kernel_launch(void* const* d_in, const int* in_sizes, int n_in,
                              void* d_out, int out_size) {
    const float* query = (const float*)d_in[0];
    const float* key   = (const float*)d_in[1];
    const float* value = (const float*)d_in[2];
    const unsigned char* mask = (const unsigned char*)d_in[3];
    const float* Wq = (const float*)d_in[4];
    const float* Wk = (const float*)d_in[5];
    const float* Wv = (const float*)d_in[6];
    const float* Wo = (const float*)d_in[7];
    const float* w1 = (const float*)d_in[8];
    const float* b1 = (const float*)d_in[9];
    const float* w2 = (const float*)d_in[10];
    const float* b2 = (const float*)d_in[11];
    const float* w3 = (const float*)d_in[12];
    const float* b3 = (const float*)d_in[13];
    const float* lng = (const float*)d_in[14];
    const float* lnb = (const float*)d_in[15];
    float* out = (float*)d_out;

    float* base = nullptr;
    cudaGetSymbolAddress((void**)&base, g_buf);
    __nv_bfloat16* wb = nullptr;
    cudaGetSymbolAddress((void**)&wb, g_wbuf);

    const size_t N = (size_t)MTOT * DIM;
    float* Qb = base;
    float* Kb = base + 1 * N;
    float* Vb = base + 2 * N;
    float* Va = base + 3 * N;
    float* T0 = base + 4 * N;
    float* X1 = base + 5 * N;
    float* H1 = base + 6 * N;
    float* X2 = base + 7 * N;

    const size_t WS = 512u * 512u;
    __nv_bfloat16* whi[7]; __nv_bfloat16* wlo[7];
    for (int i = 0; i < 7; i++) {
        whi[i] = wb + (size_t)i * 2 * WS;
        wlo[i] = whi[i] + WS;
    }

    // Weight pre-conversion (Wq..Wo need transpose; w1..w3 already [N,K])
    convw_t<<<dim3(16, 16), 256>>>(Wq, whi[0], wlo[0]);
    convw_t<<<dim3(16, 16), 256>>>(Wk, whi[1], wlo[1]);
    convw_t<<<dim3(16, 16), 256>>>(Wv, whi[2], wlo[2]);
    convw_t<<<dim3(16, 16), 256>>>(Wo, whi[3], wlo[3]);
    convw_nt<<<256, 256>>>(w1, whi[4], wlo[4]);
    convw_nt<<<256, 256>>>(w2, whi[5], wlo[5]);
    convw_nt<<<256, 256>>>(w3, whi[6], wlo[6]);

    cudaFuncSetAttribute(gemm_mma<false, false>, cudaFuncAttributeMaxDynamicSharedMemorySize, GM_SMEM);
    cudaFuncSetAttribute(gemm_mma<true, true>,   cudaFuncAttributeMaxDynamicSharedMemorySize, GM_SMEM);
    cudaFuncSetAttribute(gemm_mma<true, false>,  cudaFuncAttributeMaxDynamicSharedMemorySize, GM_SMEM);

    dim3 gg(4, 128), gb(256);

    // QKV projections (tensor cores, bf16x3 split)
    gemm_mma<false, false><<<gg, gb, GM_SMEM>>>(query, whi[0], wlo[0], nullptr, Qb);
    gemm_mma<false, false><<<gg, gb, GM_SMEM>>>(key,   whi[1], wlo[1], nullptr, Kb);
    gemm_mma<false, false><<<gg, gb, GM_SMEM>>>(value, whi[2], wlo[2], nullptr, Vb);

    // Fused attention
    const int attn_smem = 4 * 64 * 68 * (int)sizeof(float);
    cudaFuncSetAttribute(attn_kernel, cudaFuncAttributeMaxDynamicSharedMemorySize, attn_smem);
    attn_kernel<<<dim3(SEQ / 64, NH, BSZ), 256, attn_smem>>>(Qb, Kb, Vb, mask, Va);

    // Output projection + residual LN
    gemm_mma<false, false><<<gg, gb, GM_SMEM>>>(Va, whi[3], wlo[3], nullptr, T0);
    ln_residual<<<MTOT, 256>>>(query, T0, lng, lnb, X1);

    // FFN
    gemm_mma<true, true ><<<gg, gb, GM_SMEM>>>(X1, whi[4], wlo[4], b1, H1);
    gemm_mma<true, false><<<gg, gb, GM_SMEM>>>(H1, whi[5], wlo[5], b2, T0);
    ln_residual<<<MTOT, 256>>>(T0, X1, lng, lnb, X2);

    // Final projection
    gemm_mma<true, false><<<gg, gb, GM_SMEM>>>(X2, whi[6], wlo[6], b3, out);
}

// round 5
// speedup vs baseline: 1.1588x; 1.1487x over previous
#include <cuda_runtime.h>
#include <math.h>

#define BSZ   16
#define SEQ   1024
#define DIM   512
#define NH    8
#define HD    64
#define MTOT  (BSZ*SEQ)
#define NEGV  (-4294967295.0f)

__device__ float g_buf[8u * MTOT * DIM];

// ---------------------------------------------------------------------------
// GEMM: C[M,512] = A[M,512] @ B  (TRANSB -> C = A @ B^T)
// Tiles 128x64x16, 256 threads, 8x4 micro-tile per thread.  (R1 version)
// ---------------------------------------------------------------------------
template<bool TRANSB, bool BIAS, bool RELU>
__global__ void __launch_bounds__(256) gemm512(const float* __restrict__ A,
                                               const float* __restrict__ B,
                                               const float* __restrict__ bias,
                                               float* __restrict__ C) {
    __shared__ float Ast[16][132];   // A tile transposed: Ast[k][m]
    __shared__ float Bs[16][68];     // Bs[k][n]
    const int tid = threadIdx.x;
    const int tx = tid & 15, ty = tid >> 4;
    const int m0 = blockIdx.y * 128, n0 = blockIdx.x * 64;

    float acc[8][4];
#pragma unroll
    for (int i = 0; i < 8; i++)
#pragma unroll
        for (int j = 0; j < 4; j++) acc[i][j] = 0.f;

    for (int k0 = 0; k0 < 512; k0 += 16) {
        __syncthreads();
#pragma unroll
        for (int r = 0; r < 2; r++) {
            int f   = tid + r * 256;
            int row = f >> 2, k4 = f & 3;
            float4 v = *(const float4*)(A + (size_t)(m0 + row) * 512 + k0 + k4 * 4);
            Ast[k4 * 4 + 0][row] = v.x;
            Ast[k4 * 4 + 1][row] = v.y;
            Ast[k4 * 4 + 2][row] = v.z;
            Ast[k4 * 4 + 3][row] = v.w;
        }
        if (!TRANSB) {
            int kk = tid >> 4, n4 = tid & 15;
            float4 v = *(const float4*)(B + (size_t)(k0 + kk) * 512 + n0 + n4 * 4);
            *(float4*)&Bs[kk][n4 * 4] = v;
        } else {
            int n = tid >> 2, k4 = tid & 3;
            float4 v = *(const float4*)(B + (size_t)(n0 + n) * 512 + k0 + k4 * 4);
            Bs[k4 * 4 + 0][n] = v.x;
            Bs[k4 * 4 + 1][n] = v.y;
            Bs[k4 * 4 + 2][n] = v.z;
            Bs[k4 * 4 + 3][n] = v.w;
        }
        __syncthreads();
#pragma unroll
        for (int kk = 0; kk < 16; kk++) {
            float4 a0 = *(float4*)&Ast[kk][ty * 8];
            float4 a1 = *(float4*)&Ast[kk][ty * 8 + 4];
            float4 bv = *(float4*)&Bs[kk][tx * 4];
            float a[8] = {a0.x, a0.y, a0.z, a0.w, a1.x, a1.y, a1.z, a1.w};
            float bb[4] = {bv.x, bv.y, bv.z, bv.w};
#pragma unroll
            for (int i = 0; i < 8; i++)
#pragma unroll
                for (int j = 0; j < 4; j++) acc[i][j] += a[i] * bb[j];
        }
    }
#pragma unroll
    for (int i = 0; i < 8; i++) {
        int row = m0 + ty * 8 + i;
        int col = n0 + tx * 4;
        float4 v;
        v.x = acc[i][0]; v.y = acc[i][1]; v.z = acc[i][2]; v.w = acc[i][3];
        if (BIAS) {
            v.x += bias[col + 0]; v.y += bias[col + 1];
            v.z += bias[col + 2]; v.w += bias[col + 3];
        }
        if (RELU) {
            v.x = fmaxf(v.x, 0.f); v.y = fmaxf(v.y, 0.f);
            v.z = fmaxf(v.z, 0.f); v.w = fmaxf(v.w, 0.f);
        }
        *(float4*)(C + (size_t)row * 512 + col) = v;
    }
}

// ---------------------------------------------------------------------------
// Flash attention v2: 64q tile, 4x4 micro-tile, k-grouped (x4) vectorized
// inner loops: 8 LDS.128 per 64 FMA in both QK^T and PV.
// ---------------------------------------------------------------------------
__global__ void __launch_bounds__(256) attn_kernel(const float* __restrict__ Q,
                                                   const float* __restrict__ K,
                                                   const float* __restrict__ V,
                                                   const unsigned char* __restrict__ mask,
                                                   float* __restrict__ O) {
    extern __shared__ float sm[];
    float* Qs = sm;                 // Qs[q][k]   64x68
    float* Kt = sm + 64 * 68;       // Kt[k][c]   64x68 (transposed)
    float* Vs = sm + 2 * 64 * 68;   // Vs[c][d]   64x68
    float* Ps = sm + 3 * 64 * 68;   // Ps[q][c]   64x68

    const int tid = threadIdx.x;
    const int tx = tid & 15, ty = tid >> 4;
    const int q0 = blockIdx.x * 64;
    const int h  = blockIdx.y;
    const int b  = blockIdx.z;
    const float inv_temp = 1.0f / (8.0f + 1e-6f);

#pragma unroll
    for (int r = 0; r < 4; r++) {
        int f = tid + r * 256;
        int row = f >> 4, k4 = f & 15;
        float4 v = *(const float4*)(Q + ((size_t)b * SEQ + q0 + row) * DIM + h * HD + k4 * 4);
        *(float4*)&Qs[row * 68 + k4 * 4] = v;
    }

    float m[4], l[4], o[4][4];
#pragma unroll
    for (int i = 0; i < 4; i++) {
        m[i] = -INFINITY; l[i] = 0.f;
#pragma unroll
        for (int j = 0; j < 4; j++) o[i][j] = 0.f;
    }

    for (int kb = 0; kb < SEQ; kb += 64) {
        __syncthreads();
#pragma unroll
        for (int r = 0; r < 4; r++) {
            int f = tid + r * 256;
            int row = f >> 4, k4 = f & 15;
            size_t goff = ((size_t)b * SEQ + kb + row) * DIM + h * HD + k4 * 4;
            float4 kv = *(const float4*)(K + goff);
            Kt[(k4 * 4 + 0) * 68 + row] = kv.x;
            Kt[(k4 * 4 + 1) * 68 + row] = kv.y;
            Kt[(k4 * 4 + 2) * 68 + row] = kv.z;
            Kt[(k4 * 4 + 3) * 68 + row] = kv.w;
            float4 vv = *(const float4*)(V + goff);
            *(float4*)&Vs[row * 68 + k4 * 4] = vv;
        }
        __syncthreads();

        // ---- S = Q K^T : k processed in groups of 4, all-float4 LDS
        float s[4][4];
#pragma unroll
        for (int i = 0; i < 4; i++)
#pragma unroll
            for (int j = 0; j < 4; j++) s[i][j] = 0.f;
#pragma unroll 4
        for (int kk = 0; kk < 64; kk += 4) {
            float4 b0 = *(float4*)&Kt[(kk + 0) * 68 + tx * 4];
            float4 b1 = *(float4*)&Kt[(kk + 1) * 68 + tx * 4];
            float4 b2 = *(float4*)&Kt[(kk + 2) * 68 + tx * 4];
            float4 b3 = *(float4*)&Kt[(kk + 3) * 68 + tx * 4];
#pragma unroll
            for (int i = 0; i < 4; i++) {
                float4 a = *(float4*)&Qs[(ty * 4 + i) * 68 + kk];
                s[i][0] += a.x * b0.x + a.y * b1.x + a.z * b2.x + a.w * b3.x;
                s[i][1] += a.x * b0.y + a.y * b1.y + a.z * b2.y + a.w * b3.y;
                s[i][2] += a.x * b0.z + a.y * b1.z + a.z * b2.z + a.w * b3.z;
                s[i][3] += a.x * b0.w + a.y * b1.w + a.z * b2.w + a.w * b3.w;
            }
        }

        // scale + mask
        uchar4 mk = *(const uchar4*)(mask + (size_t)b * SEQ + kb + tx * 4);
        unsigned char mkb[4] = {mk.x, mk.y, mk.z, mk.w};
#pragma unroll
        for (int i = 0; i < 4; i++)
#pragma unroll
            for (int j = 0; j < 4; j++) {
                float sv = s[i][j] * inv_temp;
                s[i][j] = mkb[j] ? NEGV : sv;
            }

        // Online softmax
#pragma unroll
        for (int i = 0; i < 4; i++) {
            float tm = fmaxf(fmaxf(s[i][0], s[i][1]), fmaxf(s[i][2], s[i][3]));
#pragma unroll
            for (int off = 8; off; off >>= 1)
                tm = fmaxf(tm, __shfl_xor_sync(0xffffffffu, tm, off));
            float mn = fmaxf(m[i], tm);
            float alpha = __expf(m[i] - mn);
            m[i] = mn;
            float rs = 0.f;
#pragma unroll
            for (int j = 0; j < 4; j++) {
                float p = __expf(s[i][j] - mn);
                s[i][j] = p;
                rs += p;
            }
#pragma unroll
            for (int off = 8; off; off >>= 1)
                rs += __shfl_xor_sync(0xffffffffu, rs, off);
            l[i] = l[i] * alpha + rs;
#pragma unroll
            for (int j = 0; j < 4; j++) o[i][j] *= alpha;
            float4 pv;
            pv.x = s[i][0]; pv.y = s[i][1]; pv.z = s[i][2]; pv.w = s[i][3];
            *(float4*)&Ps[(ty * 4 + i) * 68 + tx * 4] = pv;
        }
        __syncthreads();

        // ---- O += P V : c processed in groups of 4, all-float4 LDS
#pragma unroll 4
        for (int cc = 0; cc < 64; cc += 4) {
            float4 b0 = *(float4*)&Vs[(cc + 0) * 68 + tx * 4];
            float4 b1 = *(float4*)&Vs[(cc + 1) * 68 + tx * 4];
            float4 b2 = *(float4*)&Vs[(cc + 2) * 68 + tx * 4];
            float4 b3 = *(float4*)&Vs[(cc + 3) * 68 + tx * 4];
#pragma unroll
            for (int i = 0; i < 4; i++) {
                float4 a = *(float4*)&Ps[(ty * 4 + i) * 68 + cc];
                o[i][0] += a.x * b0.x + a.y * b1.x + a.z * b2.x + a.w * b3.x;
                o[i][1] += a.x * b0.y + a.y * b1.y + a.z * b2.y + a.w * b3.y;
                o[i][2] += a.x * b0.z + a.y * b1.z + a.z * b2.z + a.w * b3.z;
                o[i][3] += a.x * b0.w + a.y * b1.w + a.z * b2.w + a.w * b3.w;
            }
        }
    }

#pragma unroll
    for (int i = 0; i < 4; i++) {
        float inv_l = 1.0f / l[i];
        float4 v;
        v.x = o[i][0] * inv_l; v.y = o[i][1] * inv_l;
        v.z = o[i][2] * inv_l; v.w = o[i][3] * inv_l;
        *(float4*)(O + ((size_t)b * SEQ + q0 + ty * 4 + i) * DIM + h * HD + tx * 4) = v;
    }
}

// ---------------------------------------------------------------------------
// Fused residual add + LayerNorm over rows of 512.
// ---------------------------------------------------------------------------
__global__ void __launch_bounds__(256) ln_residual(const float* __restrict__ A,
                                                   const float* __restrict__ Bm,
                                                   const float* __restrict__ g,
                                                   const float* __restrict__ beta,
                                                   float* __restrict__ out) {
    const int row = blockIdx.x;
    const int tid = threadIdx.x;
    const size_t base = (size_t)row * 512;
    float e0 = A[base + tid]       + Bm[base + tid];
    float e1 = A[base + tid + 256] + Bm[base + tid + 256];
    float s  = e0 + e1;
    float s2 = e0 * e0 + e1 * e1;
#pragma unroll
    for (int off = 16; off; off >>= 1) {
        s  += __shfl_xor_sync(0xffffffffu, s, off);
        s2 += __shfl_xor_sync(0xffffffffu, s2, off);
    }
    __shared__ float ws[8], ws2[8];
    const int wid = tid >> 5, lane = tid & 31;
    if (lane == 0) { ws[wid] = s; ws2[wid] = s2; }
    __syncthreads();
    float ts = 0.f, ts2 = 0.f;
#pragma unroll
    for (int w = 0; w < 8; w++) { ts += ws[w]; ts2 += ws2[w]; }
    float mu  = ts * (1.0f / 512.0f);
    float var = ts2 * (1.0f / 512.0f) - mu * mu;
    float rsd = rsqrtf(var + 1e-5f);
    out[base + tid]       = (e0 - mu) * rsd * g[tid]       + beta[tid];
    out[base + tid + 256] = (e1 - mu) * rsd * g[tid + 256] + beta[tid + 256];
}

// ---------------------------------------------------------------------------
extern "C" void kernel_launch(void* const* d_in, const int* in_sizes, int n_in,
                              void* d_out, int out_size) {
    const float* query = (const float*)d_in[0];
    const float* key   = (const float*)d_in[1];
    const float* value = (const float*)d_in[2];
    const unsigned char* mask = (const unsigned char*)d_in[3];
    const float* Wq = (const float*)d_in[4];
    const float* Wk = (const float*)d_in[5];
    const float* Wv = (const float*)d_in[6];
    const float* Wo = (const float*)d_in[7];
    const float* w1 = (const float*)d_in[8];
    const float* b1 = (const float*)d_in[9];
    const float* w2 = (const float*)d_in[10];
    const float* b2 = (const float*)d_in[11];
    const float* w3 = (const float*)d_in[12];
    const float* b3 = (const float*)d_in[13];
    const float* lng = (const float*)d_in[14];
    const float* lnb = (const float*)d_in[15];
    float* out = (float*)d_out;

    float* base = nullptr;
    cudaGetSymbolAddress((void**)&base, g_buf);
    const size_t N = (size_t)MTOT * DIM;
    float* Qb = base;
    float* Kb = base + 1 * N;
    float* Vb = base + 2 * N;
    float* Va = base + 3 * N;
    float* T0 = base + 4 * N;
    float* X1 = base + 5 * N;
    float* H1 = base + 6 * N;
    float* X2 = base + 7 * N;

    dim3 gg(8, 128), gb(256);

    // QKV projections
    gemm512<false, false, false><<<gg, gb>>>(query, Wq, nullptr, Qb);
    gemm512<false, false, false><<<gg, gb>>>(key,   Wk, nullptr, Kb);
    gemm512<false, false, false><<<gg, gb>>>(value, Wv, nullptr, Vb);

    // Fused attention
    const int attn_smem = 4 * 64 * 68 * (int)sizeof(float);  // 69632
    cudaFuncSetAttribute(attn_kernel, cudaFuncAttributeMaxDynamicSharedMemorySize, attn_smem);
    attn_kernel<<<dim3(SEQ / 64, NH, BSZ), 256, attn_smem>>>(Qb, Kb, Vb, mask, Va);

    // Output projection + residual LN
    gemm512<false, false, false><<<gg, gb>>>(Va, Wo, nullptr, T0);
    ln_residual<<<MTOT, 256>>>(query, T0, lng, lnb, X1);

    // FFN
    gemm512<true, true, true ><<<gg, gb>>>(X1, w1, b1, H1);
    gemm512<true, true, false><<<gg, gb>>>(H1, w2, b2, T0);
    ln_residual<<<MTOT, 256>>>(T0, X1, lng, lnb, X2);

    // Final projection
    gemm512<true, true, false><<<gg, gb>>>(X2, w3, b3, out);
}

// round 6
// speedup vs baseline: 1.1712x; 1.0107x over previous
#include <cuda_runtime.h>
#include <math.h>
#include <stdint.h>

#define BSZ   16
#define SEQ   1024
#define DIM   512
#define NH    8
#define HD    64
#define MTOT  (BSZ*SEQ)
#define NEGV  (-4294967295.0f)

__device__ float g_buf[8u * MTOT * DIM];

#define CP_ASYNC16(s, g) \
    asm volatile("cp.async.cg.shared.global [%0], [%1], 16;" :: "r"(s), "l"(g) : "memory")
#define CP_COMMIT()  asm volatile("cp.async.commit_group;" ::: "memory")
#define CP_WAIT0()   asm volatile("cp.async.wait_group 0;" ::: "memory")

__device__ __forceinline__ uint32_t smem_u32(const void* p) {
    uint32_t a;
    asm("{ .reg .u64 t; cvta.to.shared.u64 t, %1; cvt.u32.u64 %0, t; }" : "=r"(a) : "l"(p));
    return a;
}

// ---------------------------------------------------------------------------
// GEMM: C[M,512] = A[M,512] @ B  (TRANSB -> C = A @ B^T)
// Tiles 128x64x16, 256 threads, 8x4 micro-tile, 2-stage pipelined smem.
// ---------------------------------------------------------------------------
template<bool TRANSB, bool BIAS, bool RELU>
__global__ void __launch_bounds__(256) gemm512(const float* __restrict__ A,
                                               const float* __restrict__ B,
                                               const float* __restrict__ bias,
                                               float* __restrict__ C) {
    __shared__ __align__(16) float Ast[2][16][132];   // A transposed: [k][m]
    __shared__ __align__(16) float Bs[2][16][68];     // [k][n]
    const int tid = threadIdx.x;
    const int tx = tid & 15, ty = tid >> 4;
    const int m0 = blockIdx.y * 128, n0 = blockIdx.x * 64;

    // A load map: 2 float4 per thread
    const int ar = tid >> 2, ak = tid & 3;
    // B maps
    const int bkk = tid >> 4, bn4 = tid & 15;    // !TRANSB (cp.async)
    const int bn  = tid >> 2, bk4 = tid & 3;     // TRANSB

    float acc[8][4];
#pragma unroll
    for (int i = 0; i < 8; i++)
#pragma unroll
        for (int j = 0; j < 4; j++) acc[i][j] = 0.f;

    float4 va0, va1, vb;

    // ---- prologue: fill stage 0
    va0 = *(const float4*)(A + (size_t)(m0 + ar) * 512 + ak * 4);
    va1 = *(const float4*)(A + (size_t)(m0 + ar + 64) * 512 + ak * 4);
    if (TRANSB) {
        vb = *(const float4*)(B + (size_t)(n0 + bn) * 512 + bk4 * 4);
    } else {
        CP_ASYNC16(smem_u32(&Bs[0][bkk][bn4 * 4]),
                   B + (size_t)bkk * 512 + n0 + bn4 * 4);
        CP_COMMIT();
    }
    {
        Ast[0][ak * 4 + 0][ar] = va0.x; Ast[0][ak * 4 + 1][ar] = va0.y;
        Ast[0][ak * 4 + 2][ar] = va0.z; Ast[0][ak * 4 + 3][ar] = va0.w;
        Ast[0][ak * 4 + 0][ar + 64] = va1.x; Ast[0][ak * 4 + 1][ar + 64] = va1.y;
        Ast[0][ak * 4 + 2][ar + 64] = va1.z; Ast[0][ak * 4 + 3][ar + 64] = va1.w;
        if (TRANSB) {
            Bs[0][bk4 * 4 + 0][bn] = vb.x; Bs[0][bk4 * 4 + 1][bn] = vb.y;
            Bs[0][bk4 * 4 + 2][bn] = vb.z; Bs[0][bk4 * 4 + 3][bn] = vb.w;
        }
    }
    if (!TRANSB) CP_WAIT0();
    __syncthreads();

    for (int c = 0; c < 32; c++) {
        const int p = c & 1;
        if (c < 31) {
            const int k0 = (c + 1) * 16;
            va0 = *(const float4*)(A + (size_t)(m0 + ar) * 512 + k0 + ak * 4);
            va1 = *(const float4*)(A + (size_t)(m0 + ar + 64) * 512 + k0 + ak * 4);
            if (TRANSB) {
                vb = *(const float4*)(B + (size_t)(n0 + bn) * 512 + k0 + bk4 * 4);
            } else {
                CP_ASYNC16(smem_u32(&Bs[p ^ 1][bkk][bn4 * 4]),
                           B + (size_t)(k0 + bkk) * 512 + n0 + bn4 * 4);
                CP_COMMIT();
            }
        }

#pragma unroll
        for (int kk = 0; kk < 16; kk++) {
            float4 a0 = *(float4*)&Ast[p][kk][ty * 8];
            float4 a1 = *(float4*)&Ast[p][kk][ty * 8 + 4];
            float4 bv = *(float4*)&Bs[p][kk][tx * 4];
            float a[8] = {a0.x, a0.y, a0.z, a0.w, a1.x, a1.y, a1.z, a1.w};
            float bb[4] = {bv.x, bv.y, bv.z, bv.w};
#pragma unroll
            for (int i = 0; i < 8; i++)
#pragma unroll
                for (int j = 0; j < 4; j++) acc[i][j] += a[i] * bb[j];
        }

        if (c < 31) {
            const int q = p ^ 1;
            Ast[q][ak * 4 + 0][ar] = va0.x; Ast[q][ak * 4 + 1][ar] = va0.y;
            Ast[q][ak * 4 + 2][ar] = va0.z; Ast[q][ak * 4 + 3][ar] = va0.w;
            Ast[q][ak * 4 + 0][ar + 64] = va1.x; Ast[q][ak * 4 + 1][ar + 64] = va1.y;
            Ast[q][ak * 4 + 2][ar + 64] = va1.z; Ast[q][ak * 4 + 3][ar + 64] = va1.w;
            if (TRANSB) {
                Bs[q][bk4 * 4 + 0][bn] = vb.x; Bs[q][bk4 * 4 + 1][bn] = vb.y;
                Bs[q][bk4 * 4 + 2][bn] = vb.z; Bs[q][bk4 * 4 + 3][bn] = vb.w;
            } else {
                CP_WAIT0();
            }
            __syncthreads();
        }
    }

#pragma unroll
    for (int i = 0; i < 8; i++) {
        int row = m0 + ty * 8 + i;
        int col = n0 + tx * 4;
        float4 v;
        v.x = acc[i][0]; v.y = acc[i][1]; v.z = acc[i][2]; v.w = acc[i][3];
        if (BIAS) {
            v.x += bias[col + 0]; v.y += bias[col + 1];
            v.z += bias[col + 2]; v.w += bias[col + 3];
        }
        if (RELU) {
            v.x = fmaxf(v.x, 0.f); v.y = fmaxf(v.y, 0.f);
            v.z = fmaxf(v.z, 0.f); v.w = fmaxf(v.w, 0.f);
        }
        *(float4*)(C + (size_t)row * 512 + col) = v;
    }
}

// ---------------------------------------------------------------------------
// Flash attention v3: q-tile 128, k-tile 64, 128 threads, 8q x 8k micro-tile.
// Qs/Ps rows carry a per-row XOR chunk swizzle so 4-row broadcast loads hit
// distinct bank quads (1 crossbar phase).  16 LDS.128 per 256 FMA.
// ---------------------------------------------------------------------------
__global__ void __launch_bounds__(128) attn_kernel(const float* __restrict__ Q,
                                                   const float* __restrict__ K,
                                                   const float* __restrict__ V,
                                                   const unsigned char* __restrict__ mask,
                                                   float* __restrict__ O) {
    extern __shared__ float sm[];
    float* Qs = sm;                    // 128 x 68 (swizzled chunks)
    float* Kt = sm + 128 * 68;         // 64 x 68 (transposed: [d][c])
    float* Vs = Kt + 64 * 68;          // 64 x 68
    float* Ps = Vs + 64 * 68;          // 128 x 68 (swizzled chunks)

    const int tid = threadIdx.x;
    const int tx = tid & 7;            // key/d group (8 cols)
    const int ty = tid >> 3;           // query group (0..15, 8 rows)
    const int sw = (ty & 3) * 4;       // per-row-group chunk swizzle (floats)
    const int q0 = blockIdx.x * 128;
    const int h  = blockIdx.y;
    const int b  = blockIdx.z;
    const float inv_temp = 1.0f / (8.0f + 1e-6f);

    // ---- load Q tile 128x64 (swizzled)
#pragma unroll
    for (int it = 0; it < 16; it++) {
        int f = tid + it * 128;
        int row = f >> 4, c = f & 15;
        float4 v = *(const float4*)(Q + ((size_t)b * SEQ + q0 + row) * DIM + h * HD + c * 4);
        int rsw = ((row >> 3) & 3) * 4;
        *(float4*)&Qs[row * 68 + ((c * 4) ^ rsw)] = v;
    }

    float m[8], l[8], o[8][8];
#pragma unroll
    for (int i = 0; i < 8; i++) {
        m[i] = -INFINITY; l[i] = 0.f;
#pragma unroll
        for (int j = 0; j < 8; j++) o[i][j] = 0.f;
    }

    for (int kb = 0; kb < SEQ; kb += 64) {
        __syncthreads();   // prev tile fully consumed (incl. PV reads of Ps)
        // ---- load K (transposed) + V tiles
#pragma unroll
        for (int it = 0; it < 8; it++) {
            int f = tid + it * 128;
            int row = f >> 4, c = f & 15;
            size_t goff = ((size_t)b * SEQ + kb + row) * DIM + h * HD + c * 4;
            float4 kv = *(const float4*)(K + goff);
            Kt[(c * 4 + 0) * 68 + row] = kv.x;
            Kt[(c * 4 + 1) * 68 + row] = kv.y;
            Kt[(c * 4 + 2) * 68 + row] = kv.z;
            Kt[(c * 4 + 3) * 68 + row] = kv.w;
            float4 vv = *(const float4*)(V + goff);
            *(float4*)&Vs[row * 68 + c * 4] = vv;
        }
        __syncthreads();

        // ---- S = Q K^T  (8q x 8k per thread), kk in groups of 4
        float s[8][8];
#pragma unroll
        for (int i = 0; i < 8; i++)
#pragma unroll
            for (int j = 0; j < 8; j++) s[i][j] = 0.f;

#pragma unroll 2
        for (int kk = 0; kk < 64; kk += 4) {
            float bb[4][8];
#pragma unroll
            for (int u = 0; u < 4; u++) {
                float4 b0 = *(float4*)&Kt[(kk + u) * 68 + tx * 8];
                float4 b1 = *(float4*)&Kt[(kk + u) * 68 + tx * 8 + 4];
                bb[u][0] = b0.x; bb[u][1] = b0.y; bb[u][2] = b0.z; bb[u][3] = b0.w;
                bb[u][4] = b1.x; bb[u][5] = b1.y; bb[u][6] = b1.z; bb[u][7] = b1.w;
            }
#pragma unroll
            for (int i = 0; i < 8; i++) {
                float4 a = *(float4*)&Qs[(ty * 8 + i) * 68 + (kk ^ sw)];
#pragma unroll
                for (int j = 0; j < 8; j++)
                    s[i][j] += a.x * bb[0][j] + a.y * bb[1][j] + a.z * bb[2][j] + a.w * bb[3][j];
            }
        }

        // ---- scale + mask (cols kb + tx*8 .. +7)
        unsigned long long mk8 = *(const unsigned long long*)(mask + (size_t)b * SEQ + kb + tx * 8);
#pragma unroll
        for (int j = 0; j < 8; j++) {
            bool masked = ((mk8 >> (8 * j)) & 0xffu) != 0;
#pragma unroll
            for (int i = 0; i < 8; i++) {
                float sv = s[i][j] * inv_temp;
                s[i][j] = masked ? NEGV : sv;
            }
        }

        // ---- online softmax (row spread over 8 lanes via tx)
#pragma unroll
        for (int i = 0; i < 8; i++) {
            float tm = s[i][0];
#pragma unroll
            for (int j = 1; j < 8; j++) tm = fmaxf(tm, s[i][j]);
            tm = fmaxf(tm, __shfl_xor_sync(0xffffffffu, tm, 4));
            tm = fmaxf(tm, __shfl_xor_sync(0xffffffffu, tm, 2));
            tm = fmaxf(tm, __shfl_xor_sync(0xffffffffu, tm, 1));
            float mn = fmaxf(m[i], tm);
            float alpha = __expf(m[i] - mn);
            m[i] = mn;
            float rs = 0.f;
#pragma unroll
            for (int j = 0; j < 8; j++) {
                float p = __expf(s[i][j] - mn);
                s[i][j] = p;
                rs += p;
            }
            rs += __shfl_xor_sync(0xffffffffu, rs, 4);
            rs += __shfl_xor_sync(0xffffffffu, rs, 2);
            rs += __shfl_xor_sync(0xffffffffu, rs, 1);
            l[i] = l[i] * alpha + rs;
#pragma unroll
            for (int j = 0; j < 8; j++) o[i][j] *= alpha;
            int row = ty * 8 + i;
            *(float4*)&Ps[row * 68 + ((tx * 8) ^ sw)] =
                make_float4(s[i][0], s[i][1], s[i][2], s[i][3]);
            *(float4*)&Ps[row * 68 + ((tx * 8 + 4) ^ sw)] =
                make_float4(s[i][4], s[i][5], s[i][6], s[i][7]);
        }
        __syncthreads();

        // ---- O += P V  (8q x 8d per thread), cc in groups of 4
#pragma unroll 2
        for (int cc = 0; cc < 64; cc += 4) {
            float bb[4][8];
#pragma unroll
            for (int u = 0; u < 4; u++) {
                float4 b0 = *(float4*)&Vs[(cc + u) * 68 + tx * 8];
                float4 b1 = *(float4*)&Vs[(cc + u) * 68 + tx * 8 + 4];
                bb[u][0] = b0.x; bb[u][1] = b0.y; bb[u][2] = b0.z; bb[u][3] = b0.w;
                bb[u][4] = b1.x; bb[u][5] = b1.y; bb[u][6] = b1.z; bb[u][7] = b1.w;
            }
#pragma unroll
            for (int i = 0; i < 8; i++) {
                float4 a = *(float4*)&Ps[(ty * 8 + i) * 68 + (cc ^ sw)];
#pragma unroll
                for (int j = 0; j < 8; j++)
                    o[i][j] += a.x * bb[0][j] + a.y * bb[1][j] + a.z * bb[2][j] + a.w * bb[3][j];
            }
        }
    }

    // ---- write V_att[b][q][h*64 + d]
#pragma unroll
    for (int i = 0; i < 8; i++) {
        float inv_l = 1.0f / l[i];
        float* dst = O + ((size_t)b * SEQ + q0 + ty * 8 + i) * DIM + h * HD + tx * 8;
        *(float4*)dst = make_float4(o[i][0] * inv_l, o[i][1] * inv_l,
                                    o[i][2] * inv_l, o[i][3] * inv_l);
        *(float4*)(dst + 4) = make_float4(o[i][4] * inv_l, o[i][5] * inv_l,
                                          o[i][6] * inv_l, o[i][7] * inv_l);
    }
}

// ---------------------------------------------------------------------------
// Fused residual add + LayerNorm over rows of 512.
// ---------------------------------------------------------------------------
__global__ void __launch_bounds__(256) ln_residual(const float* __restrict__ A,
                                                   const float* __restrict__ Bm,
                                                   const float* __restrict__ g,
                                                   const float* __restrict__ beta,
                                                   float* __restrict__ out) {
    const int row = blockIdx.x;
    const int tid = threadIdx.x;
    const size_t base = (size_t)row * 512;
    float e0 = A[base + tid]       + Bm[base + tid];
    float e1 = A[base + tid + 256] + Bm[base + tid + 256];
    float s  = e0 + e1;
    float s2 = e0 * e0 + e1 * e1;
#pragma unroll
    for (int off = 16; off; off >>= 1) {
        s  += __shfl_xor_sync(0xffffffffu, s, off);
        s2 += __shfl_xor_sync(0xffffffffu, s2, off);
    }
    __shared__ float ws[8], ws2[8];
    const int wid = tid >> 5, lane = tid & 31;
    if (lane == 0) { ws[wid] = s; ws2[wid] = s2; }
    __syncthreads();
    float ts = 0.f, ts2 = 0.f;
#pragma unroll
    for (int w = 0; w < 8; w++) { ts += ws[w]; ts2 += ws2[w]; }
    float mu  = ts * (1.0f / 512.0f);
    float var = ts2 * (1.0f / 512.0f) - mu * mu;
    float rsd = rsqrtf(var + 1e-5f);
    out[base + tid]       = (e0 - mu) * rsd * g[tid]       + beta[tid];
    out[base + tid + 256] = (e1 - mu) * rsd * g[tid + 256] + beta[tid + 256];
}

// ---------------------------------------------------------------------------
extern "C" void kernel_launch(void* const* d_in, const int* in_sizes, int n_in,
                              void* d_out, int out_size) {
    const float* query = (const float*)d_in[0];
    const float* key   = (const float*)d_in[1];
    const float* value = (const float*)d_in[2];
    const unsigned char* mask = (const unsigned char*)d_in[3];
    const float* Wq = (const float*)d_in[4];
    const float* Wk = (const float*)d_in[5];
    const float* Wv = (const float*)d_in[6];
    const float* Wo = (const float*)d_in[7];
    const float* w1 = (const float*)d_in[8];
    const float* b1 = (const float*)d_in[9];
    const float* w2 = (const float*)d_in[10];
    const float* b2 = (const float*)d_in[11];
    const float* w3 = (const float*)d_in[12];
    const float* b3 = (const float*)d_in[13];
    const float* lng = (const float*)d_in[14];
    const float* lnb = (const float*)d_in[15];
    float* out = (float*)d_out;

    float* base = nullptr;
    cudaGetSymbolAddress((void**)&base, g_buf);
    const size_t N = (size_t)MTOT * DIM;
    float* Qb = base;
    float* Kb = base + 1 * N;
    float* Vb = base + 2 * N;
    float* Va = base + 3 * N;
    float* T0 = base + 4 * N;
    float* X1 = base + 5 * N;
    float* H1 = base + 6 * N;
    float* X2 = base + 7 * N;

    dim3 gg(8, 128), gb(256);

    // QKV projections
    gemm512<false, false, false><<<gg, gb>>>(query, Wq, nullptr, Qb);
    gemm512<false, false, false><<<gg, gb>>>(key,   Wk, nullptr, Kb);
    gemm512<false, false, false><<<gg, gb>>>(value, Wv, nullptr, Vb);

    // Fused attention: 128q tiles, 128 threads
    const int attn_smem = 68 * (128 + 64 + 64 + 128) * (int)sizeof(float);  // 104448
    cudaFuncSetAttribute(attn_kernel, cudaFuncAttributeMaxDynamicSharedMemorySize, attn_smem);
    attn_kernel<<<dim3(SEQ / 128, NH, BSZ), 128, attn_smem>>>(Qb, Kb, Vb, mask, Va);

    // Output projection + residual LN
    gemm512<false, false, false><<<gg, gb>>>(Va, Wo, nullptr, T0);
    ln_residual<<<MTOT, 256>>>(query, T0, lng, lnb, X1);

    // FFN
    gemm512<true, true, true ><<<gg, gb>>>(X1, w1, b1, H1);
    gemm512<true, true, false><<<gg, gb>>>(H1, w2, b2, T0);
    ln_residual<<<MTOT, 256>>>(T0, X1, lng, lnb, X2);

    // Final projection
    gemm512<true, true, false><<<gg, gb>>>(X2, w3, b3, out);
}

// round 9
// speedup vs baseline: 1.6697x; 1.4256x over previous
#include <cuda_runtime.h>
#include <cuda_bf16.h>
#include <math.h>
#include <stdint.h>

#define BSZ   16
#define SEQ   1024
#define DIM   512
#define NH    8
#define HD    64
#define MTOT  (BSZ*SEQ)
#define NEGV  (-4294967295.0f)

__device__ float g_buf[8u * MTOT * DIM];                 // fp32 activations
__device__ __nv_bfloat16 g_wbuf[7u * 2u * 512u * 512u];  // weights bf16 hi/lo [N,K]
__device__ __nv_bfloat16 g_abuf[2u * MTOT * DIM];        // activation bf16 hi/lo (reused)

// ---------------------------------------------------------------------------
// helpers
// ---------------------------------------------------------------------------
__device__ __forceinline__ uint32_t smem_u32(const void* p) {
    uint32_t a;
    asm("{ .reg .u64 t; cvta.to.shared.u64 t, %1; cvt.u32.u64 %0, t; }" : "=r"(a) : "l"(p));
    return a;
}
__device__ __forceinline__ void ldsm_x4(uint32_t& r0, uint32_t& r1, uint32_t& r2, uint32_t& r3, uint32_t a) {
    asm volatile("ldmatrix.sync.aligned.m8n8.x4.shared.b16 {%0,%1,%2,%3}, [%4];"
                 : "=r"(r0), "=r"(r1), "=r"(r2), "=r"(r3) : "r"(a));
}
__device__ __forceinline__ void ldsm_x2(uint32_t& r0, uint32_t& r1, uint32_t a) {
    asm volatile("ldmatrix.sync.aligned.m8n8.x2.shared.b16 {%0,%1}, [%2];"
                 : "=r"(r0), "=r"(r1) : "r"(a));
}
__device__ __forceinline__ void mma_bf16(float* d, const uint32_t* a, const uint32_t* b) {
    asm volatile("mma.sync.aligned.m16n8k16.row.col.f32.bf16.bf16.f32 "
                 "{%0,%1,%2,%3}, {%4,%5,%6,%7}, {%8,%9}, {%0,%1,%2,%3};"
                 : "+f"(d[0]), "+f"(d[1]), "+f"(d[2]), "+f"(d[3])
                 : "r"(a[0]), "r"(a[1]), "r"(a[2]), "r"(a[3]), "r"(b[0]), "r"(b[1]));
}
#define CP_ASYNC16(s, g) \
    asm volatile("cp.async.cg.shared.global [%0], [%1], 16;" :: "r"(s), "l"(g) : "memory")
#define CP_COMMIT()  asm volatile("cp.async.commit_group;" ::: "memory")
#define CP_WAIT0()   asm volatile("cp.async.wait_group 0;" ::: "memory")

__device__ __forceinline__ void split1(float x, unsigned short& h, unsigned short& l) {
    __nv_bfloat16 hb = __float2bfloat16(x);
    float r = x - __bfloat162float(hb);
    __nv_bfloat16 lb = __float2bfloat16(r);
    h = __bfloat16_as_ushort(hb);
    l = __bfloat16_as_ushort(lb);
}

// ---------------------------------------------------------------------------
// Activation split: fp32 [M,512] -> bf16 hi/lo
// ---------------------------------------------------------------------------
__global__ void __launch_bounds__(256) splitf(const float* __restrict__ in,
                                              __nv_bfloat16* __restrict__ hi,
                                              __nv_bfloat16* __restrict__ lo) {
    int i = blockIdx.x * 256 + threadIdx.x;   // float4 index
    float4 v = ((const float4*)in)[i];
    unsigned short h[4], l[4];
    split1(v.x, h[0], l[0]); split1(v.y, h[1], l[1]);
    split1(v.z, h[2], l[2]); split1(v.w, h[3], l[3]);
    uint2 hp = make_uint2((uint32_t)h[0] | ((uint32_t)h[1] << 16),
                          (uint32_t)h[2] | ((uint32_t)h[3] << 16));
    uint2 lp = make_uint2((uint32_t)l[0] | ((uint32_t)l[1] << 16),
                          (uint32_t)l[2] | ((uint32_t)l[3] << 16));
    *(uint2*)(hi + (size_t)i * 4) = hp;
    *(uint2*)(lo + (size_t)i * 4) = lp;
}

// ---------------------------------------------------------------------------
// Weight conversion: bf16 hi/lo in [N,K] K-major
// ---------------------------------------------------------------------------
__global__ void __launch_bounds__(256) convw_nt(const float* __restrict__ in,
                                                __nv_bfloat16* __restrict__ hi,
                                                __nv_bfloat16* __restrict__ lo) {
    int i = blockIdx.x * 256 + threadIdx.x;
    float4 v = ((const float4*)in)[i];
    unsigned short h[4], l[4];
    split1(v.x, h[0], l[0]); split1(v.y, h[1], l[1]);
    split1(v.z, h[2], l[2]); split1(v.w, h[3], l[3]);
    uint2 hp = make_uint2((uint32_t)h[0] | ((uint32_t)h[1] << 16),
                          (uint32_t)h[2] | ((uint32_t)h[3] << 16));
    uint2 lp = make_uint2((uint32_t)l[0] | ((uint32_t)l[1] << 16),
                          (uint32_t)l[2] | ((uint32_t)l[3] << 16));
    *(uint2*)(hi + (size_t)i * 4) = hp;
    *(uint2*)(lo + (size_t)i * 4) = lp;
}

__global__ void __launch_bounds__(256) convw_t(const float* __restrict__ in,
                                               __nv_bfloat16* __restrict__ hi,
                                               __nv_bfloat16* __restrict__ lo) {
    __shared__ float t[32][33];
    const int bx = blockIdx.x * 32;   // k block
    const int by = blockIdx.y * 32;   // n block
    const int tx = threadIdx.x & 31, tr = threadIdx.x >> 5;
#pragma unroll
    for (int i = 0; i < 4; i++) {
        int r = tr + i * 8;
        t[r][tx] = in[(size_t)(bx + r) * 512 + by + tx];
    }
    __syncthreads();
#pragma unroll
    for (int i = 0; i < 4; i++) {
        int r = tr + i * 8;
        float x = t[tx][r];
        unsigned short h, l;
        split1(x, h, l);
        size_t o = (size_t)(by + r) * 512 + bx + tx;
        hi[o] = __ushort_as_bfloat16(h);
        lo[o] = __ushort_as_bfloat16(l);
    }
}

// ---------------------------------------------------------------------------
// Pure-bf16 HMMA GEMM: C[M,512] = Ah@Bh^T + Ah@Bl^T + Al@Bh^T (fp32 acc)
// CTA 128x128, 8 warps (2m x 4n), warp tile 64x32, K-chunks of 32,
// 2-stage cp.async pipeline. RS=80B rows (conflict-free ldmatrix).
// ---------------------------------------------------------------------------
#define RS      80
#define OFF_AH  0
#define OFF_AL  10240
#define OFF_BH  20480
#define OFF_BL  30720
#define STG     40960
#define GM_SMEM (2 * STG)

template<bool BIAS, bool RELU>
__global__ void __launch_bounds__(256) gemm_bf3(const __nv_bfloat16* __restrict__ Ah,
                                                const __nv_bfloat16* __restrict__ Al,
                                                const __nv_bfloat16* __restrict__ Bh,
                                                const __nv_bfloat16* __restrict__ Bl,
                                                const float* __restrict__ bias,
                                                float* __restrict__ C) {
    extern __shared__ __align__(128) char smem[];
    const uint32_t sb = smem_u32(smem);
    const int tid = threadIdx.x;
    const int lane = tid & 31, wid = tid >> 5;
    const int wm = wid >> 2, wn = wid & 3;
    const int m0 = blockIdx.y * 128, n0 = blockIdx.x * 128;

    float acc[4][4][4];
#pragma unroll
    for (int i = 0; i < 4; i++)
#pragma unroll
        for (int j = 0; j < 4; j++)
#pragma unroll
            for (int v = 0; v < 4; v++) acc[i][j][v] = 0.f;

    // chunk loader: 512 f-values, r = f>>2 (0..127), q = f&3 (4 x 16B per row)
    auto issue = [&](int c, int p) {
        const uint32_t base = sb + p * STG;
#pragma unroll
        for (int i = 0; i < 2; i++) {
            int f = tid + i * 256;           // 0..511
            int r = f >> 2, q = f & 3;
            uint32_t so = (uint32_t)(r * RS + q * 16);
            size_t gA = (size_t)(m0 + r) * 512 + c * 32 + q * 8;
            size_t gB = (size_t)(n0 + r) * 512 + c * 32 + q * 8;
            CP_ASYNC16(base + OFF_AH + so, Ah + gA);
            CP_ASYNC16(base + OFF_AL + so, Al + gA);
            CP_ASYNC16(base + OFF_BH + so, Bh + gB);
            CP_ASYNC16(base + OFF_BL + so, Bl + gB);
        }
        CP_COMMIT();
    };

    issue(0, 0);
    CP_WAIT0();
    __syncthreads();

    for (int c = 0; c < 16; c++) {
        const int p = c & 1;
        if (c < 15) issue(c + 1, p ^ 1);

        const uint32_t stg = sb + p * STG;
#pragma unroll
        for (int kk = 0; kk < 2; kk++) {
            uint32_t bh[4][2], bl[4][2];
#pragma unroll
            for (int nt = 0; nt < 4; nt++) {
                uint32_t boff = (uint32_t)((wn * 32 + nt * 8 + (lane & 7)) * RS +
                                           (kk * 16 + ((lane >> 3) & 1) * 8) * 2);
                ldsm_x2(bh[nt][0], bh[nt][1], stg + OFF_BH + boff);
                ldsm_x2(bl[nt][0], bl[nt][1], stg + OFF_BL + boff);
            }
#pragma unroll
            for (int mt = 0; mt < 4; mt++) {
                uint32_t aoff = (uint32_t)((wm * 64 + mt * 16 + (lane & 15)) * RS +
                                           (kk * 16 + ((lane >> 4) & 1) * 8) * 2);
                uint32_t ah[4], al[4];
                ldsm_x4(ah[0], ah[1], ah[2], ah[3], stg + OFF_AH + aoff);
                ldsm_x4(al[0], al[1], al[2], al[3], stg + OFF_AL + aoff);
#pragma unroll
                for (int nt = 0; nt < 4; nt++) {
                    mma_bf16(acc[mt][nt], ah, bh[nt]);
                    mma_bf16(acc[mt][nt], ah, bl[nt]);
                    mma_bf16(acc[mt][nt], al, bh[nt]);
                }
            }
        }

        if (c < 15) {
            CP_WAIT0();
            __syncthreads();
        }
    }

    // epilogue (R4-validated mapping)
#pragma unroll
    for (int mt = 0; mt < 4; mt++) {
#pragma unroll
        for (int nt = 0; nt < 4; nt++) {
            int r0 = m0 + wm * 64 + mt * 16 + (lane >> 2);
            int cc = n0 + wn * 32 + nt * 8 + 2 * (lane & 3);
            float d0 = acc[mt][nt][0], d1 = acc[mt][nt][1];
            float d2 = acc[mt][nt][2], d3 = acc[mt][nt][3];
            if (BIAS) {
                float b0 = bias[cc], b1 = bias[cc + 1];
                d0 += b0; d1 += b1; d2 += b0; d3 += b1;
            }
            if (RELU) {
                d0 = fmaxf(d0, 0.f); d1 = fmaxf(d1, 0.f);
                d2 = fmaxf(d2, 0.f); d3 = fmaxf(d3, 0.f);
            }
            *(float2*)(C + (size_t)r0 * 512 + cc)       = make_float2(d0, d1);
            *(float2*)(C + (size_t)(r0 + 8) * 512 + cc) = make_float2(d2, d3);
        }
    }
}

// ---------------------------------------------------------------------------
// Flash attention (R1 version — best measured): 64q tile, 4x4 micro-tile.
// ---------------------------------------------------------------------------
__global__ void __launch_bounds__(256) attn_kernel(const float* __restrict__ Q,
                                                   const float* __restrict__ K,
                                                   const float* __restrict__ V,
                                                   const unsigned char* __restrict__ mask,
                                                   float* __restrict__ O) {
    extern __shared__ float sm[];
    float* Qs = sm;
    float* Kt = sm + 64 * 68;
    float* Vs = sm + 2 * 64 * 68;
    float* Ps = sm + 3 * 64 * 68;

    const int tid = threadIdx.x;
    const int tx = tid & 15, ty = tid >> 4;
    const int q0 = blockIdx.x * 64;
    const int h  = blockIdx.y;
    const int b  = blockIdx.z;
    const float inv_temp = 1.0f / (8.0f + 1e-6f);

#pragma unroll
    for (int r = 0; r < 4; r++) {
        int f = tid + r * 256;
        int row = f >> 4, k4 = f & 15;
        float4 v = *(const float4*)(Q + ((size_t)b * SEQ + q0 + row) * DIM + h * HD + k4 * 4);
        *(float4*)&Qs[row * 68 + k4 * 4] = v;
    }

    float m[4], l[4], o[4][4];
#pragma unroll
    for (int i = 0; i < 4; i++) {
        m[i] = -INFINITY; l[i] = 0.f;
#pragma unroll
        for (int j = 0; j < 4; j++) o[i][j] = 0.f;
    }

    for (int kb = 0; kb < SEQ; kb += 64) {
        __syncthreads();
#pragma unroll
        for (int r = 0; r < 4; r++) {
            int f = tid + r * 256;
            int row = f >> 4, k4 = f & 15;
            size_t goff = ((size_t)b * SEQ + kb + row) * DIM + h * HD + k4 * 4;
            float4 kv = *(const float4*)(K + goff);
            Kt[(k4 * 4 + 0) * 68 + row] = kv.x;
            Kt[(k4 * 4 + 1) * 68 + row] = kv.y;
            Kt[(k4 * 4 + 2) * 68 + row] = kv.z;
            Kt[(k4 * 4 + 3) * 68 + row] = kv.w;
            float4 vv = *(const float4*)(V + goff);
            *(float4*)&Vs[row * 68 + k4 * 4] = vv;
        }
        __syncthreads();

        float s[4][4];
#pragma unroll
        for (int i = 0; i < 4; i++)
#pragma unroll
            for (int j = 0; j < 4; j++) s[i][j] = 0.f;
#pragma unroll
        for (int kk = 0; kk < 64; kk++) {
            float4 bv = *(float4*)&Kt[kk * 68 + tx * 4];
            float bb[4] = {bv.x, bv.y, bv.z, bv.w};
#pragma unroll
            for (int i = 0; i < 4; i++) {
                float a = Qs[(ty * 4 + i) * 68 + kk];
#pragma unroll
                for (int j = 0; j < 4; j++) s[i][j] += a * bb[j];
            }
        }
        uchar4 mk = *(const uchar4*)(mask + (size_t)b * SEQ + kb + tx * 4);
        unsigned char mkb[4] = {mk.x, mk.y, mk.z, mk.w};
#pragma unroll
        for (int i = 0; i < 4; i++)
#pragma unroll
            for (int j = 0; j < 4; j++) {
                float sv = s[i][j] * inv_temp;
                s[i][j] = mkb[j] ? NEGV : sv;
            }

#pragma unroll
        for (int i = 0; i < 4; i++) {
            float tm = fmaxf(fmaxf(s[i][0], s[i][1]), fmaxf(s[i][2], s[i][3]));
#pragma unroll
            for (int off = 8; off; off >>= 1)
                tm = fmaxf(tm, __shfl_xor_sync(0xffffffffu, tm, off));
            float mn = fmaxf(m[i], tm);
            float alpha = __expf(m[i] - mn);
            m[i] = mn;
            float rs = 0.f;
#pragma unroll
            for (int j = 0; j < 4; j++) {
                float p = __expf(s[i][j] - mn);
                s[i][j] = p;
                rs += p;
            }
#pragma unroll
            for (int off = 8; off; off >>= 1)
                rs += __shfl_xor_sync(0xffffffffu, rs, off);
            l[i] = l[i] * alpha + rs;
#pragma unroll
            for (int j = 0; j < 4; j++) o[i][j] *= alpha;
            float4 pv;
            pv.x = s[i][0]; pv.y = s[i][1]; pv.z = s[i][2]; pv.w = s[i][3];
            *(float4*)&Ps[(ty * 4 + i) * 68 + tx * 4] = pv;
        }
        __syncthreads();

#pragma unroll
        for (int cc = 0; cc < 64; cc++) {
            float4 bv = *(float4*)&Vs[cc * 68 + tx * 4];
            float bb[4] = {bv.x, bv.y, bv.z, bv.w};
#pragma unroll
            for (int i = 0; i < 4; i++) {
                float a = Ps[(ty * 4 + i) * 68 + cc];
#pragma unroll
                for (int j = 0; j < 4; j++) o[i][j] += a * bb[j];
            }
        }
    }

#pragma unroll
    for (int i = 0; i < 4; i++) {
        float inv_l = 1.0f / l[i];
        float4 v;
        v.x = o[i][0] * inv_l; v.y = o[i][1] * inv_l;
        v.z = o[i][2] * inv_l; v.w = o[i][3] * inv_l;
        *(float4*)(O + ((size_t)b * SEQ + q0 + ty * 4 + i) * DIM + h * HD + tx * 4) = v;
    }
}

// ---------------------------------------------------------------------------
// Fused residual add + LayerNorm over rows of 512.
// ---------------------------------------------------------------------------
__global__ void __launch_bounds__(256) ln_residual(const float* __restrict__ A,
                                                   const float* __restrict__ Bm,
                                                   const float* __restrict__ g,
                                                   const float* __restrict__ beta,
                                                   float* __restrict__ out) {
    const int row = blockIdx.x;
    const int tid = threadIdx.x;
    const size_t base = (size_t)row * 512;
    float e0 = A[base + tid]       + Bm[base + tid];
    float e1 = A[base + tid + 256] + Bm[base + tid + 256];
    float s  = e0 + e1;
    float s2 = e0 * e0 + e1 * e1;
#pragma unroll
    for (int off = 16; off; off >>= 1) {
        s  += __shfl_xor_sync(0xffffffffu, s, off);
        s2 += __shfl_xor_sync(0xffffffffu, s2, off);
    }
    __shared__ float ws[8], ws2[8];
    const int wid = tid >> 5, lane = tid & 31;
    if (lane == 0) { ws[wid] = s; ws2[wid] = s2; }
    __syncthreads();
    float ts = 0.f, ts2 = 0.f;
#pragma unroll
    for (int w = 0; w < 8; w++) { ts += ws[w]; ts2 += ws2[w]; }
    float mu  = ts * (1.0f / 512.0f);
    float var = ts2 * (1.0f / 512.0f) - mu * mu;
    float rsd = rsqrtf(var + 1e-5f);
    out[base + tid]       = (e0 - mu) * rsd * g[tid]       + beta[tid];
    out[base + tid + 256] = (e1 - mu) * rsd * g[tid + 256] + beta[tid + 256];
}

// ---------------------------------------------------------------------------
extern "C" void kernel_launch(void* const* d_in, const int* in_sizes, int n_in,
                              void* d_out, int out_size) {
    const float* query = (const float*)d_in[0];
    const float* key   = (const float*)d_in[1];
    const float* value = (const float*)d_in[2];
    const unsigned char* mask = (const unsigned char*)d_in[3];
    const float* Wq = (const float*)d_in[4];
    const float* Wk = (const float*)d_in[5];
    const float* Wv = (const float*)d_in[6];
    const float* Wo = (const float*)d_in[7];
    const float* w1 = (const float*)d_in[8];
    const float* b1 = (const float*)d_in[9];
    const float* w2 = (const float*)d_in[10];
    const float* b2 = (const float*)d_in[11];
    const float* w3 = (const float*)d_in[12];
    const float* b3 = (const float*)d_in[13];
    const float* lng = (const float*)d_in[14];
    const float* lnb = (const float*)d_in[15];
    float* out = (float*)d_out;

    float* base = nullptr;
    cudaGetSymbolAddress((void**)&base, g_buf);
    __nv_bfloat16* wb = nullptr;
    cudaGetSymbolAddress((void**)&wb, g_wbuf);
    __nv_bfloat16* ab = nullptr;
    cudaGetSymbolAddress((void**)&ab, g_abuf);

    const size_t N = (size_t)MTOT * DIM;
    float* Qb = base;
    float* Kb = base + 1 * N;
    float* Vb = base + 2 * N;
    float* Va = base + 3 * N;
    float* T0 = base + 4 * N;
    float* X1 = base + 5 * N;
    float* H1 = base + 6 * N;
    float* X2 = base + 7 * N;

    __nv_bfloat16* ah = ab;
    __nv_bfloat16* al = ab + N;

    const size_t WS = 512u * 512u;
    __nv_bfloat16* whi[7]; __nv_bfloat16* wlo[7];
    for (int i = 0; i < 7; i++) {
        whi[i] = wb + (size_t)i * 2 * WS;
        wlo[i] = whi[i] + WS;
    }

    // Weight pre-conversion
    convw_t<<<dim3(16, 16), 256>>>(Wq, whi[0], wlo[0]);
    convw_t<<<dim3(16, 16), 256>>>(Wk, whi[1], wlo[1]);
    convw_t<<<dim3(16, 16), 256>>>(Wv, whi[2], wlo[2]);
    convw_t<<<dim3(16, 16), 256>>>(Wo, whi[3], wlo[3]);
    convw_nt<<<256, 256>>>(w1, whi[4], wlo[4]);
    convw_nt<<<256, 256>>>(w2, whi[5], wlo[5]);
    convw_nt<<<256, 256>>>(w3, whi[6], wlo[6]);

    cudaFuncSetAttribute(gemm_bf3<false, false>, cudaFuncAttributeMaxDynamicSharedMemorySize, GM_SMEM);
    cudaFuncSetAttribute(gemm_bf3<true, true>,   cudaFuncAttributeMaxDynamicSharedMemorySize, GM_SMEM);
    cudaFuncSetAttribute(gemm_bf3<true, false>,  cudaFuncAttributeMaxDynamicSharedMemorySize, GM_SMEM);

    dim3 gg(4, 128), gb(256);
    const int SPLIT_GRID = (int)(N / 4 / 256);

    // QKV projections
    splitf<<<SPLIT_GRID, 256>>>(query, ah, al);
    gemm_bf3<false, false><<<gg, gb, GM_SMEM>>>(ah, al, whi[0], wlo[0], nullptr, Qb);
    splitf<<<SPLIT_GRID, 256>>>(key, ah, al);
    gemm_bf3<false, false><<<gg, gb, GM_SMEM>>>(ah, al, whi[1], wlo[1], nullptr, Kb);
    splitf<<<SPLIT_GRID, 256>>>(value, ah, al);
    gemm_bf3<false, false><<<gg, gb, GM_SMEM>>>(ah, al, whi[2], wlo[2], nullptr, Vb);

    // Fused attention (fp32, R1)
    const int attn_smem = 4 * 64 * 68 * (int)sizeof(float);
    cudaFuncSetAttribute(attn_kernel, cudaFuncAttributeMaxDynamicSharedMemorySize, attn_smem);
    attn_kernel<<<dim3(SEQ / 64, NH, BSZ), 256, attn_smem>>>(Qb, Kb, Vb, mask, Va);

    // Output projection + residual LN
    splitf<<<SPLIT_GRID, 256>>>(Va, ah, al);
    gemm_bf3<false, false><<<gg, gb, GM_SMEM>>>(ah, al, whi[3], wlo[3], nullptr, T0);
    ln_residual<<<MTOT, 256>>>(query, T0, lng, lnb, X1);

    // FFN
    splitf<<<SPLIT_GRID, 256>>>(X1, ah, al);
    gemm_bf3<true, true ><<<gg, gb, GM_SMEM>>>(ah, al, whi[4], wlo[4], b1, H1);
    splitf<<<SPLIT_GRID, 256>>>(H1, ah, al);
    gemm_bf3<true, false><<<gg, gb, GM_SMEM>>>(ah, al, whi[5], wlo[5], b2, T0);
    ln_residual<<<MTOT, 256>>>(T0, X1, lng, lnb, X2);

    // Final projection
    splitf<<<SPLIT_GRID, 256>>>(X2, ah, al);
    gemm_bf3<true, false><<<gg, gb, GM_SMEM>>>(ah, al, whi[6], wlo[6], b3, out);
}